// round 2
// baseline (speedup 1.0000x reference)
#include <cuda_runtime.h>
#include <math.h>

// ---------------------------------------------------------------------------
// TemporalPromptGeneratorModel — fp32 baseline with algebraic reductions:
//  * attention == V (seq-len-1 softmax) -> fold Wv@Wo into W_eff (400x400)
//  * GRU h0==0 -> recurrent weights dead; GRU = elementwise on flat@K
//  * final cat GEMM = 3 accumulating GEMMs
// ---------------------------------------------------------------------------

#define BM 128
#define BN 128
#define BK 8
#define TM 8
#define TN 8

// ------------------------- scratch (device globals) ------------------------
__device__ float g_Weff[400 * 400];
__device__ float g_beff[400];
__device__ float g_attn[16383 * 400];
__device__ float g_flat[16384 * 1600];
__device__ float g_G[16384 * 5400];          // GRU preact scratch (reused f/b)
__device__ float g_x1[16384 * 3600];
__device__ float g_x3[16384 * 1800];
__device__ float g_x5[16384 * 1800];

// ------------------------------- SGEMM -------------------------------------
// C[M,N] = A[M,K] @ B[K,N]  (+bias) (+accumulate C) (+elu) | split-K atomic
// flags: bit0 accumulate into C, bit1 elu epilogue, bit2 split-K atomicAdd
__global__ __launch_bounds__(256, 2)
void sgemm_kernel(const float* __restrict__ A, const float* __restrict__ B,
                  float* __restrict__ C, const float* __restrict__ bias,
                  int M, int N, int K, int lda, int ldb, int ldc,
                  int flags, int kChunk)
{
    __shared__ float As[BK][BM];
    __shared__ float Bs[BK][BN];

    const int tid = threadIdx.x;
    const int tx = tid & 15;          // 0..15  (col micro)
    const int ty = tid >> 4;          // 0..15  (row micro)
    const int rowBase = blockIdx.y * BM;
    const int colBase = blockIdx.x * BN;

    const int kStart = blockIdx.z * kChunk;
    const int kEnd = min(kStart + kChunk, K);

    float acc[TM][TN];
#pragma unroll
    for (int i = 0; i < TM; i++)
#pragma unroll
        for (int j = 0; j < TN; j++) acc[i][j] = 0.f;

    // A tile: 128x8, one float4 per thread (along K). K is always %8==0.
    const int aRow = tid >> 1;
    const int aCol = (tid & 1) * 4;
    const int gARow = rowBase + aRow;
    // B tile: 8x128, one float4 per thread (along N). N is always %4==0.
    const int bRow = tid >> 5;
    const int bCol = (tid & 31) * 4;
    const int gBCol = colBase + bCol;

    for (int k0 = kStart; k0 < kEnd; k0 += BK) {
        float4 av = make_float4(0.f, 0.f, 0.f, 0.f);
        if (gARow < M)
            av = *reinterpret_cast<const float4*>(A + (size_t)gARow * lda + k0 + aCol);
        As[aCol + 0][aRow] = av.x;
        As[aCol + 1][aRow] = av.y;
        As[aCol + 2][aRow] = av.z;
        As[aCol + 3][aRow] = av.w;

        float4 bv = make_float4(0.f, 0.f, 0.f, 0.f);
        if (gBCol < N)
            bv = *reinterpret_cast<const float4*>(B + (size_t)(k0 + bRow) * ldb + gBCol);
        *reinterpret_cast<float4*>(&Bs[bRow][bCol]) = bv;
        __syncthreads();

#pragma unroll
        for (int kk = 0; kk < BK; kk++) {
            float4 a0 = *reinterpret_cast<const float4*>(&As[kk][ty * TM]);
            float4 a1 = *reinterpret_cast<const float4*>(&As[kk][ty * TM + 4]);
            float4 b0 = *reinterpret_cast<const float4*>(&Bs[kk][tx * TN]);
            float4 b1 = *reinterpret_cast<const float4*>(&Bs[kk][tx * TN + 4]);
            float a[TM] = {a0.x, a0.y, a0.z, a0.w, a1.x, a1.y, a1.z, a1.w};
            float b[TN] = {b0.x, b0.y, b0.z, b0.w, b1.x, b1.y, b1.z, b1.w};
#pragma unroll
            for (int i = 0; i < TM; i++)
#pragma unroll
                for (int j = 0; j < TN; j++)
                    acc[i][j] = fmaf(a[i], b[j], acc[i][j]);
        }
        __syncthreads();
    }

#pragma unroll
    for (int i = 0; i < TM; i++) {
        int row = rowBase + ty * TM + i;
        if (row >= M) continue;
#pragma unroll
        for (int j = 0; j < TN; j++) {
            int col = colBase + tx * TN + j;
            if (col >= N) continue;
            float v = acc[i][j];
            size_t off = (size_t)row * ldc + col;
            if (flags & 4) {
                atomicAdd(&C[off], v);
            } else {
                if (bias) v += bias[col];
                if (flags & 1) v += C[off];
                if (flags & 2) v = (v > 0.f) ? v : expm1f(v);
                C[off] = v;
            }
        }
    }
}

// ------------------------- small helper kernels ----------------------------
__global__ void zero_weff_kernel()
{
    int i = blockIdx.x * 256 + threadIdx.x;
    if (i < 400 * 400) g_Weff[i] = 0.f;
}

// b_eff[d] = bo[d] + sum_j bv[j] * Wo_flat[j, d]
__global__ void beff_kernel(const float* __restrict__ bv,
                            const float* __restrict__ Wo,
                            const float* __restrict__ bo)
{
    int d = blockIdx.x * 256 + threadIdx.x;
    if (d >= 400) return;
    float acc = bo[d];
    for (int j = 0; j < 6400; j++)
        acc = fmaf(bv[j], Wo[(size_t)j * 400 + d], acc);
    g_beff[d] = acc;
}

// flat[b, 0:1200] = x[b]; flat[0, 1200:1600] = x[0,2,:]
__global__ void build_flat_base(const float* __restrict__ x)
{
    int idx = blockIdx.x * 256 + threadIdx.x;
    const int total = 16384 * 1200;
    if (idx < total) {
        int b = idx / 1200, c = idx - b * 1200;
        g_flat[(size_t)b * 1600 + c] = x[idx];
    } else if (idx < total + 400) {
        int d = idx - total;
        g_flat[1200 + d] = x[800 + d];
    }
}

__device__ __forceinline__ float blockReduceSum(float v, float* sh)
{
#pragma unroll
    for (int o = 16; o > 0; o >>= 1) v += __shfl_xor_sync(0xffffffffu, v, o);
    int lane = threadIdx.x & 31, warp = threadIdx.x >> 5;
    if (lane == 0) sh[warp] = v;
    __syncthreads();
    if (warp == 0) {
        float r = (lane < 8) ? sh[lane] : 0.f;
#pragma unroll
        for (int o = 4; o > 0; o >>= 1) r += __shfl_xor_sync(0xffffffffu, r, o);
        if (lane == 0) sh[0] = r;
    }
    __syncthreads();
    float r = sh[0];
    __syncthreads();
    return r;
}

// Per encoder row b (0..16382): LN1(xe+attn) -> rank-2 FFN -> LN2 -> flat[b+1]
__global__ __launch_bounds__(256)
void frontend_kernel(const float* __restrict__ x,
                     const float* __restrict__ ln1g, const float* __restrict__ ln1b,
                     const float* __restrict__ w1,  const float* __restrict__ fb1,
                     const float* __restrict__ w2,  const float* __restrict__ fb2,
                     const float* __restrict__ ln2g, const float* __restrict__ ln2b)
{
    int b = blockIdx.x;
    const float* xe = x + (size_t)(b + 1) * 1200 + 800;
    const float* at = g_attn + (size_t)b * 400;
    __shared__ float red[32];
    int t = threadIdx.x;

    float sv[2], o1[2], s2v[2];
    int dIdx[2];
    int cnt = 0;
    float sum = 0.f, sq = 0.f;
    for (int d = t; d < 400; d += 256) {
        float v = xe[d] + at[d];
        sv[cnt] = v; dIdx[cnt] = d; cnt++;
        sum += v; sq += v * v;
    }
    sum = blockReduceSum(sum, red);
    sq  = blockReduceSum(sq, red);
    float mean = sum * (1.f / 400.f);
    float var  = sq * (1.f / 400.f) - mean * mean;
    float rstd = rsqrtf(var + 1e-6f);

    float t0 = 0.f, t1 = 0.f;
    for (int i = 0; i < cnt; i++) {
        int d = dIdx[i];
        float o = (sv[i] - mean) * rstd * ln1g[d] + ln1b[d];
        o1[i] = o;
        t0 = fmaf(o, w1[2 * d], t0);
        t1 = fmaf(o, w1[2 * d + 1], t1);
    }
    t0 = blockReduceSum(t0, red);
    t1 = blockReduceSum(t1, red);
    t0 = fmaxf(t0 + fb1[0], 0.f);
    t1 = fmaxf(t1 + fb1[1], 0.f);

    sum = 0.f; sq = 0.f;
    for (int i = 0; i < cnt; i++) {
        int d = dIdx[i];
        float v = o1[i] + t0 * w2[d] + t1 * w2[400 + d] + fb2[d];
        s2v[i] = v; sum += v; sq += v * v;
    }
    sum = blockReduceSum(sum, red);
    sq  = blockReduceSum(sq, red);
    mean = sum * (1.f / 400.f);
    var  = sq * (1.f / 400.f) - mean * mean;
    rstd = rsqrtf(var + 1e-6f);

    float* dst = g_flat + (size_t)(b + 1) * 1600 + 1200;
    for (int i = 0; i < cnt; i++) {
        int d = dIdx[i];
        dst[d] = (s2v[i] - mean) * rstd * ln2g[d] + ln2b[d];
    }
}

// GRU elementwise (h0 == 0): h = (1 - sigmoid(xz+rz)) * elu(xh + sigmoid(xr+rr)*rh)
__global__ void gru_elem_kernel(const float* __restrict__ Brow1, int colOff)
{
    int idx = blockIdx.x * 256 + threadIdx.x;
    if (idx >= 16384 * 1800) return;
    int b = idx / 1800, j = idx - b * 1800;
    const float* g = g_G + (size_t)b * 5400;
    float z = 1.f / (1.f + expf(-(g[j] + Brow1[j])));
    float r = 1.f / (1.f + expf(-(g[1800 + j] + Brow1[1800 + j])));
    float hv = g[3600 + j] + r * Brow1[3600 + j];
    float hh = (hv > 0.f) ? hv : expm1f(hv);
    g_x1[(size_t)b * 3600 + colOff + j] = (1.f - z) * hh;
}

// ------------------------------- host side ---------------------------------
static void launch_sgemm(const float* A, const float* B, float* C, const float* bias,
                         int M, int N, int K, int lda, int ldb, int ldc,
                         int flags, int splitK)
{
    dim3 grid((N + BN - 1) / BN, (M + BM - 1) / BM, splitK);
    int kChunk = (splitK > 1) ? (((K / splitK) + BK - 1) / BK) * BK : K;
    sgemm_kernel<<<grid, 256>>>(A, B, C, bias, M, N, K, lda, ldb, ldc, flags, kChunk);
}

extern "C" void kernel_launch(void* const* d_in, const int* in_sizes, int n_in,
                              void* d_out, int out_size)
{
    (void)n_in; (void)out_size;
    const float* x  = (const float*)d_in[0];
    const float* Wv = (const float*)d_in[5];
    const float* bv = (const float*)d_in[6];
    const float* Wo = (const float*)d_in[7];
    const float* bo = (const float*)d_in[8];

    // Input-order disambiguation: signature order has ln1_b (400 elems) at idx 10,
    // setup_inputs dict order has ffn_w1 (800 elems) there.
    bool sigOrder = (in_sizes[10] == 400);
    const float *ln1g, *ln1b, *w1, *fb1, *w2, *fb2, *ln2g, *ln2b;
    const float *gfk, *gfb, *gbk, *gbb, *d2w, *d2b, *d4w, *d4b, *ow, *ob;
    if (sigOrder) {
        ln1g = (const float*)d_in[9];  ln1b = (const float*)d_in[10];
        w1   = (const float*)d_in[11]; fb1  = (const float*)d_in[12];
        w2   = (const float*)d_in[13]; fb2  = (const float*)d_in[14];
        ln2g = (const float*)d_in[15]; ln2b = (const float*)d_in[16];
        gfk  = (const float*)d_in[17]; gfb  = (const float*)d_in[19];
        gbk  = (const float*)d_in[20]; gbb  = (const float*)d_in[22];
        d2w  = (const float*)d_in[23]; d2b  = (const float*)d_in[24];
        d4w  = (const float*)d_in[25]; d4b  = (const float*)d_in[26];
        ow   = (const float*)d_in[27]; ob   = (const float*)d_in[28];
    } else {
        ln1b = (const float*)d_in[9];
        w1   = (const float*)d_in[10]; fb1  = (const float*)d_in[11];
        w2   = (const float*)d_in[12]; fb2  = (const float*)d_in[13];
        ln2b = (const float*)d_in[14];
        gfk  = (const float*)d_in[15]; gfb  = (const float*)d_in[17];
        gbk  = (const float*)d_in[18]; gbb  = (const float*)d_in[20];
        d2w  = (const float*)d_in[21]; d2b  = (const float*)d_in[22];
        d4w  = (const float*)d_in[23]; d4b  = (const float*)d_in[24];
        ow   = (const float*)d_in[25]; ob   = (const float*)d_in[26];
        ln1g = (const float*)d_in[27]; ln2g = (const float*)d_in[28];
    }

    float *pWeff, *pattn, *pflat, *pG, *px1, *px3, *px5;
    cudaGetSymbolAddress((void**)&pWeff, g_Weff);
    cudaGetSymbolAddress((void**)&pattn, g_attn);
    cudaGetSymbolAddress((void**)&pflat, g_flat);
    cudaGetSymbolAddress((void**)&pG,    g_G);
    cudaGetSymbolAddress((void**)&px1,   g_x1);
    cudaGetSymbolAddress((void**)&px3,   g_x3);
    cudaGetSymbolAddress((void**)&px5,   g_x5);
    float* pbeff;
    cudaGetSymbolAddress((void**)&pbeff, g_beff);

    float* out = (float*)d_out;

    // 1) W_eff = Wv_flat(400x6400) @ Wo_flat(6400x400)  (split-K atomic)
    zero_weff_kernel<<<(400 * 400 + 255) / 256, 256>>>();
    launch_sgemm(Wv, Wo, pWeff, nullptr, 400, 400, 6400, 6400, 400, 400, /*flags*/4, /*splitK*/8);
    // 2) b_eff = bv @ Wo_flat + bo
    beff_kernel<<<2, 256>>>(bv, Wo, bo);
    // 3) attn = xe @ W_eff + b_eff   (xe: rows 1..16383, timestep 2 -> offset 2000, lda=1200)
    launch_sgemm(x + 2000, pWeff, pattn, pbeff, 16383, 400, 400, 1200, 400, 400, 0, 1);
    // 4) flat base = x (and row0 output)
    build_flat_base<<<(16384 * 1200 + 400 + 255) / 256, 256>>>(x);
    // 5) encoder frontend -> flat[:,1200:1600]
    frontend_kernel<<<16383, 256>>>(x, ln1g, ln1b, w1, fb1, w2, fb2, ln2g, ln2b);
    // 6) forward GRU: G = flat @ gru_fk + gru_fb[0];  x1[:, :1800]
    launch_sgemm(pflat, gfk, pG, gfb, 16384, 5400, 1600, 1600, 5400, 5400, 0, 1);
    gru_elem_kernel<<<(16384 * 1800 + 255) / 256, 256>>>(gfb + 5400, 0);
    // 7) backward GRU: G = flat @ gru_bk + gru_bb[0];  x1[:, 1800:]
    launch_sgemm(pflat, gbk, pG, gbb, 16384, 5400, 1600, 1600, 5400, 5400, 0, 1);
    gru_elem_kernel<<<(16384 * 1800 + 255) / 256, 256>>>(gbb + 5400, 1800);
    // 8) x3 = elu(x1 @ d2_w + d2_b)
    launch_sgemm(px1, d2w, px3, d2b, 16384, 1800, 3600, 3600, 1800, 1800, /*elu*/2, 1);
    // 9) x5 = elu(x3 @ d4_w + d4_b)
    launch_sgemm(px3, d4w, px5, d4b, 16384, 1800, 1800, 1800, 1800, 1800, /*elu*/2, 1);
    // 10) out = x1@W[0:3600] + x3@W[3600:5400] + x5@W[5400:7200] + out_b
    launch_sgemm(px1, ow,              out, ob,      16384, 140, 3600, 3600, 140, 140, 0, 1);
    launch_sgemm(px3, ow + 3600 * 140, out, nullptr, 16384, 140, 1800, 1800, 140, 140, /*acc*/1, 1);
    launch_sgemm(px5, ow + 5400 * 140, out, nullptr, 16384, 140, 1800, 1800, 140, 140, /*acc*/1, 1);
}

// round 6
// speedup vs baseline: 2.4182x; 2.4182x over previous
#include <cuda_runtime.h>
#include <cuda_bf16.h>
#include <math.h>
#include <stdint.h>

typedef __nv_bfloat16 bf16;

// ============================ scratch ============================
__device__ float g_Weff[400 * 400];
__device__ float g_beff[400];
__device__ float g_attn[16383 * 400];
__device__ float g_G[(size_t)16384 * 5504];
__device__ bf16  g_flatH[(size_t)16384 * 1600];
__device__ bf16  g_flatL[(size_t)16384 * 1600];
__device__ bf16  g_x1H[(size_t)16384 * 3648];
__device__ bf16  g_x1L[(size_t)16384 * 3648];
__device__ bf16  g_x3H[(size_t)16384 * 1920];
__device__ bf16  g_x3L[(size_t)16384 * 1920];
__device__ bf16  g_x5H[(size_t)16384 * 1920];
__device__ bf16  g_x5L[(size_t)16384 * 1920];
__device__ bf16  g_BgfH[(size_t)5504 * 1600];
__device__ bf16  g_BgfL[(size_t)5504 * 1600];
__device__ bf16  g_BgbH[(size_t)5504 * 1600];
__device__ bf16  g_BgbL[(size_t)5504 * 1600];
__device__ bf16  g_Bd2H[(size_t)1920 * 3648];
__device__ bf16  g_Bd2L[(size_t)1920 * 3648];
__device__ bf16  g_Bd4H[(size_t)1920 * 1920];
__device__ bf16  g_Bd4L[(size_t)1920 * 1920];
__device__ bf16  g_BoH[(size_t)256 * 7488];
__device__ bf16  g_BoL[(size_t)256 * 7488];

// ============================ ptx helpers (plain sm_103-legal) ============================
__device__ __forceinline__ uint32_t s2u(const void* p) {
    uint32_t a;
    asm("{ .reg .u64 t; cvta.to.shared.u64 t, %1; cvt.u32.u64 %0, t; }" : "=r"(a) : "l"(p));
    return a;
}
__device__ __forceinline__ void ldm_x4(uint32_t* r, uint32_t addr) {
    asm volatile("ldmatrix.sync.aligned.m8n8.x4.shared.b16 {%0,%1,%2,%3}, [%4];"
                 : "=r"(r[0]), "=r"(r[1]), "=r"(r[2]), "=r"(r[3]) : "r"(addr));
}
__device__ __forceinline__ void mma16816(float* c, const uint32_t* a, const uint32_t* b) {
    asm volatile("mma.sync.aligned.m16n8k16.row.col.f32.bf16.bf16.f32 "
                 "{%0,%1,%2,%3}, {%4,%5,%6,%7}, {%8,%9}, {%0,%1,%2,%3};"
                 : "+f"(c[0]), "+f"(c[1]), "+f"(c[2]), "+f"(c[3])
                 : "r"(a[0]), "r"(a[1]), "r"(a[2]), "r"(a[3]), "r"(b[0]), "r"(b[1]));
}
__device__ __forceinline__ void cp16(uint32_t saddr, const void* g) {
    asm volatile("cp.async.cg.shared.global [%0], [%1], 16;" :: "r"(saddr), "l"(g) : "memory");
}

// ============================ HMMA GEMM ============================
// C[16384, 128*gridX] = concat(A1|A2|A3)[16384, Ktot] @ Bt[Npad, Ktot]^T
// bf16 hi/lo 3-term compensation, fp32 register accum.
// EPI 0: C = acc + bias(col<biasN). EPI 1: elu(acc+bias) -> bf16 hi/lo OH/OL.
// EPI 2: C[col<Nvalid] = acc + bias.
#define PITCH 40               // bf16 elems per smem row (80B; conflict-free)
#define TILE_B (128 * PITCH * 2)   // 10240
#define STAGE_B (4 * TILE_B)       // 40960

template<int EPI>
__global__ __launch_bounds__(256, 1)
void hmma_gemm(const bf16* __restrict__ A1H, const bf16* __restrict__ A1L,
               const bf16* __restrict__ A2H, const bf16* __restrict__ A2L,
               const bf16* __restrict__ A3H, const bf16* __restrict__ A3L,
               int lda1, int lda2, int lda3, int kb1, int kb2, int Ktot,
               const bf16* __restrict__ BH, const bf16* __restrict__ BL, int ldb,
               float* __restrict__ C, int ldc,
               const float* __restrict__ bias, int biasN,
               bf16* __restrict__ OH, bf16* __restrict__ OL, int ldo, int Nvalid)
{
    extern __shared__ char smem[];
    const uint32_t su = s2u(smem);
    const int tid = threadIdx.x;
    const int lane = tid & 31;
    const int wid = tid >> 5;
    const int warp_m = wid & 1;       // 2 x 64 rows
    const int warp_n = wid >> 1;      // 4 x 32 cols
    const size_t rowA = (size_t)blockIdx.y * 128;
    const size_t rowB = (size_t)blockIdx.x * 128;
    const int NCH = Ktot / 32;

    // loader indices: 2 x float4 per tile per thread
    const int ldRow0 = tid >> 2, ldC0 = (tid & 3);          // idx = tid
    const int ldRow1 = (tid + 256) >> 2, ldC1 = ldC0;       // idx = tid + 256

    // issue cp.async for chunk ch into stage s
    auto issue = [&](int ch, int s) {
        const int k0 = ch * 32;
        const bf16 *pAH, *pAL; int kl; size_t lda;
        if (k0 < kb1)      { pAH = A1H; pAL = A1L; kl = k0;       lda = (size_t)lda1; }
        else if (k0 < kb2) { pAH = A2H; pAL = A2L; kl = k0 - kb1; lda = (size_t)lda2; }
        else               { pAH = A3H; pAL = A3L; kl = k0 - kb2; lda = (size_t)lda3; }
        uint32_t st = su + s * STAGE_B;
        uint32_t d0 = st + ldRow0 * (PITCH * 2) + ldC0 * 16;
        uint32_t d1 = st + ldRow1 * (PITCH * 2) + ldC1 * 16;
        size_t a0 = (rowA + ldRow0) * lda + kl + ldC0 * 8;
        size_t a1 = (rowA + ldRow1) * lda + kl + ldC1 * 8;
        size_t b0 = (rowB + ldRow0) * (size_t)ldb + k0 + ldC0 * 8;
        size_t b1 = (rowB + ldRow1) * (size_t)ldb + k0 + ldC1 * 8;
        cp16(d0,              pAH + a0);  cp16(d1,              pAH + a1);
        cp16(d0 + TILE_B,     pAL + a0);  cp16(d1 + TILE_B,     pAL + a1);
        cp16(d0 + 2 * TILE_B, BH  + b0);  cp16(d1 + 2 * TILE_B, BH  + b1);
        cp16(d0 + 3 * TILE_B, BL  + b0);  cp16(d1 + 3 * TILE_B, BL  + b1);
        asm volatile("cp.async.commit_group;" ::: "memory");
    };

    float acc[4][4][4];
#pragma unroll
    for (int i = 0; i < 4; i++)
#pragma unroll
        for (int j = 0; j < 4; j++)
#pragma unroll
            for (int k = 0; k < 4; k++) acc[i][j][k] = 0.f;

    issue(0, 0);

    const int aLRow = lane & 15, aKH = lane >> 4;
    const int bRow = (lane & 7) + ((lane >> 4) << 3);
    const int bKH = (lane >> 3) & 1;

    for (int ch = 0; ch < NCH; ch++) {
        const int s = ch & 1;
        if (ch + 1 < NCH) {
            issue(ch + 1, s ^ 1);
            asm volatile("cp.async.wait_group 1;" ::: "memory");
        } else {
            asm volatile("cp.async.wait_group 0;" ::: "memory");
        }
        __syncthreads();

        const uint32_t st = su + s * STAGE_B;
#pragma unroll
        for (int kk2 = 0; kk2 < 2; kk2++) {
            const int kcol = kk2 * 16;
            uint32_t aH[4][4], aL[4][4];
#pragma unroll
            for (int mf = 0; mf < 4; mf++) {
                uint32_t ad = st + (warp_m * 64 + mf * 16 + aLRow) * (PITCH * 2) + (kcol + 8 * aKH) * 2;
                ldm_x4(aH[mf], ad);
                ldm_x4(aL[mf], ad + TILE_B);
            }
            uint32_t bHf[4][2], bLf[4][2];
#pragma unroll
            for (int np = 0; np < 2; np++) {
                uint32_t ad = st + 2 * TILE_B + (warp_n * 32 + np * 16 + bRow) * (PITCH * 2) + (kcol + 8 * bKH) * 2;
                uint32_t t[4];
                ldm_x4(t, ad);
                bHf[np * 2][0] = t[0]; bHf[np * 2][1] = t[1];
                bHf[np * 2 + 1][0] = t[2]; bHf[np * 2 + 1][1] = t[3];
                ldm_x4(t, ad + TILE_B);
                bLf[np * 2][0] = t[0]; bLf[np * 2][1] = t[1];
                bLf[np * 2 + 1][0] = t[2]; bLf[np * 2 + 1][1] = t[3];
            }
#pragma unroll
            for (int mf = 0; mf < 4; mf++)
#pragma unroll
                for (int nf = 0; nf < 4; nf++) {
                    mma16816(acc[mf][nf], aH[mf], bHf[nf]);
                    mma16816(acc[mf][nf], aH[mf], bLf[nf]);
                    mma16816(acc[mf][nf], aL[mf], bHf[nf]);
                }
        }
        __syncthreads();
    }

    // ---------------- epilogue ----------------
    const int rBase = (int)rowA + warp_m * 64 + (lane >> 2);
    const int cBase = (int)rowB + warp_n * 32 + (lane & 3) * 2;
#pragma unroll
    for (int mf = 0; mf < 4; mf++) {
#pragma unroll
        for (int half = 0; half < 2; half++) {
            const size_t r = rBase + mf * 16 + half * 8;
#pragma unroll
            for (int nf = 0; nf < 4; nf++) {
                const int col = cBase + nf * 8;
                float v0 = acc[mf][nf][half * 2 + 0];
                float v1 = acc[mf][nf][half * 2 + 1];
                if (EPI == 0) {
                    if (col + 0 < biasN) v0 += bias[col + 0];
                    if (col + 1 < biasN) v1 += bias[col + 1];
                    *reinterpret_cast<float2*>(C + r * (size_t)ldc + col) = make_float2(v0, v1);
                } else if (EPI == 1) {
                    if (col + 0 < biasN) v0 += bias[col + 0];
                    if (col + 1 < biasN) v1 += bias[col + 1];
                    v0 = v0 > 0.f ? v0 : expm1f(v0);
                    v1 = v1 > 0.f ? v1 : expm1f(v1);
                    bf16 h0 = __float2bfloat16(v0), h1 = __float2bfloat16(v1);
                    bf16 l0 = __float2bfloat16(v0 - __bfloat162float(h0));
                    bf16 l1 = __float2bfloat16(v1 - __bfloat162float(h1));
                    uint32_t hp = (uint32_t)__bfloat16_as_ushort(h0) | ((uint32_t)__bfloat16_as_ushort(h1) << 16);
                    uint32_t lp = (uint32_t)__bfloat16_as_ushort(l0) | ((uint32_t)__bfloat16_as_ushort(l1) << 16);
                    *reinterpret_cast<uint32_t*>(OH + r * (size_t)ldo + col) = hp;
                    *reinterpret_cast<uint32_t*>(OL + r * (size_t)ldo + col) = lp;
                } else {
                    if (col + 0 < Nvalid) C[r * (size_t)ldc + col + 0] = v0 + bias[col + 0];
                    if (col + 1 < Nvalid) C[r * (size_t)ldc + col + 1] = v1 + bias[col + 1];
                }
            }
        }
    }
}

// ============================ weight transpose + split ============================
__global__ void convB_kernel(const float* __restrict__ B, int Ksrc, int Nsrc, int ldbsrc,
                             bf16* __restrict__ BtH, bf16* __restrict__ BtL, int ldbt, int kOff)
{
    __shared__ float t[32][33];
    int k0 = blockIdx.x * 32, n0 = blockIdx.y * 32;
    int tx = threadIdx.x, ty = threadIdx.y;
#pragma unroll
    for (int i = 0; i < 4; i++) {
        int k = k0 + ty + i * 8, n = n0 + tx;
        t[ty + i * 8][tx] = (k < Ksrc && n < Nsrc) ? B[(size_t)k * ldbsrc + n] : 0.f;
    }
    __syncthreads();
#pragma unroll
    for (int i = 0; i < 4; i++) {
        int n = n0 + ty + i * 8, k = k0 + tx;
        float v = t[tx][ty + i * 8];
        bf16 h = __float2bfloat16(v);
        size_t o = (size_t)n * ldbt + kOff + k;
        BtH[o] = h;
        BtL[o] = __float2bfloat16(v - __bfloat162float(h));
    }
}

// ============================ SIMT SGEMM (front-end only) ============================
#define BM 128
#define BN 128
#define BK 8
__global__ __launch_bounds__(256, 2)
void sgemm_kernel(const float* __restrict__ A, const float* __restrict__ B,
                  float* __restrict__ C, const float* __restrict__ bias,
                  int M, int N, int K, int lda, int ldb, int ldc, int flags, int kChunk)
{
    __shared__ float As[BK][BM];
    __shared__ float Bs[BK][BN];
    const int tid = threadIdx.x;
    const int tx = tid & 15, ty = tid >> 4;
    const int rowBase = blockIdx.y * BM, colBase = blockIdx.x * BN;
    const int kStart = blockIdx.z * kChunk;
    const int kEnd = min(kStart + kChunk, K);
    float acc[8][8];
#pragma unroll
    for (int i = 0; i < 8; i++)
#pragma unroll
        for (int j = 0; j < 8; j++) acc[i][j] = 0.f;
    const int aRow = tid >> 1, aCol = (tid & 1) * 4, gARow = rowBase + aRow;
    const int bRow = tid >> 5, bCol = (tid & 31) * 4, gBCol = colBase + bCol;
    for (int k0 = kStart; k0 < kEnd; k0 += BK) {
        float4 av = make_float4(0.f, 0.f, 0.f, 0.f);
        if (gARow < M) av = *reinterpret_cast<const float4*>(A + (size_t)gARow * lda + k0 + aCol);
        As[aCol + 0][aRow] = av.x; As[aCol + 1][aRow] = av.y;
        As[aCol + 2][aRow] = av.z; As[aCol + 3][aRow] = av.w;
        float4 bv = make_float4(0.f, 0.f, 0.f, 0.f);
        if (gBCol < N) bv = *reinterpret_cast<const float4*>(B + (size_t)(k0 + bRow) * ldb + gBCol);
        *reinterpret_cast<float4*>(&Bs[bRow][bCol]) = bv;
        __syncthreads();
#pragma unroll
        for (int kk = 0; kk < BK; kk++) {
            float4 a0 = *reinterpret_cast<const float4*>(&As[kk][ty * 8]);
            float4 a1 = *reinterpret_cast<const float4*>(&As[kk][ty * 8 + 4]);
            float4 b0 = *reinterpret_cast<const float4*>(&Bs[kk][tx * 8]);
            float4 b1 = *reinterpret_cast<const float4*>(&Bs[kk][tx * 8 + 4]);
            float a[8] = {a0.x, a0.y, a0.z, a0.w, a1.x, a1.y, a1.z, a1.w};
            float b[8] = {b0.x, b0.y, b0.z, b0.w, b1.x, b1.y, b1.z, b1.w};
#pragma unroll
            for (int i = 0; i < 8; i++)
#pragma unroll
                for (int j = 0; j < 8; j++) acc[i][j] = fmaf(a[i], b[j], acc[i][j]);
        }
        __syncthreads();
    }
#pragma unroll
    for (int i = 0; i < 8; i++) {
        int row = rowBase + ty * 8 + i;
        if (row >= M) continue;
#pragma unroll
        for (int j = 0; j < 8; j++) {
            int col = colBase + tx * 8 + j;
            if (col >= N) continue;
            float v = acc[i][j];
            size_t off = (size_t)row * ldc + col;
            if (flags & 4) atomicAdd(&C[off], v);
            else { if (bias) v += bias[col]; C[off] = v; }
        }
    }
}

// ============================ small helpers ============================
__global__ void zero_weff_kernel()
{
    int i = blockIdx.x * 256 + threadIdx.x;
    if (i < 400 * 400) g_Weff[i] = 0.f;
}
__global__ void beff_kernel(const float* __restrict__ bv, const float* __restrict__ Wo,
                            const float* __restrict__ bo)
{
    int d = blockIdx.x * 256 + threadIdx.x;
    if (d >= 400) return;
    float acc = bo[d];
    for (int j = 0; j < 6400; j++) acc = fmaf(bv[j], Wo[(size_t)j * 400 + d], acc);
    g_beff[d] = acc;
}
__global__ void build_flat_bf16(const float* __restrict__ x)
{
    int idx = blockIdx.x * 256 + threadIdx.x;
    const int total = 16384 * 1200;
    float v; size_t dst;
    if (idx < total) {
        int b = idx / 1200, c = idx - b * 1200;
        v = x[idx]; dst = (size_t)b * 1600 + c;
    } else if (idx < total + 400) {
        int d = idx - total;
        v = x[800 + d]; dst = 1200 + d;
    } else return;
    bf16 h = __float2bfloat16(v);
    g_flatH[dst] = h;
    g_flatL[dst] = __float2bfloat16(v - __bfloat162float(h));
}
__global__ void pad_x1_kernel()
{
    int i = blockIdx.x * 256 + threadIdx.x;
    if (i >= 16384 * 48) return;
    int b = i / 48, c = 3600 + i % 48;
    size_t o = (size_t)b * 3648 + c;
    g_x1H[o] = __float2bfloat16(0.f);
    g_x1L[o] = __float2bfloat16(0.f);
}

__device__ __forceinline__ float blockReduceSum(float v, float* sh)
{
#pragma unroll
    for (int o = 16; o > 0; o >>= 1) v += __shfl_xor_sync(0xffffffffu, v, o);
    int lane = threadIdx.x & 31, warp = threadIdx.x >> 5;
    if (lane == 0) sh[warp] = v;
    __syncthreads();
    if (warp == 0) {
        float r = (lane < 8) ? sh[lane] : 0.f;
#pragma unroll
        for (int o = 4; o > 0; o >>= 1) r += __shfl_xor_sync(0xffffffffu, r, o);
        if (lane == 0) sh[0] = r;
    }
    __syncthreads();
    float r = sh[0];
    __syncthreads();
    return r;
}

__global__ __launch_bounds__(256)
void frontend_kernel(const float* __restrict__ x,
                     const float* __restrict__ ln1g, const float* __restrict__ ln1b,
                     const float* __restrict__ w1,  const float* __restrict__ fb1,
                     const float* __restrict__ w2,  const float* __restrict__ fb2,
                     const float* __restrict__ ln2g, const float* __restrict__ ln2b)
{
    int b = blockIdx.x;
    const float* xe = x + (size_t)(b + 1) * 1200 + 800;
    const float* at = g_attn + (size_t)b * 400;
    __shared__ float red[32];
    int t = threadIdx.x;
    float sv[2], o1[2], s2v[2];
    int dIdx[2], cnt = 0;
    float sum = 0.f, sq = 0.f;
    for (int d = t; d < 400; d += 256) {
        float v = xe[d] + at[d];
        sv[cnt] = v; dIdx[cnt] = d; cnt++;
        sum += v; sq += v * v;
    }
    sum = blockReduceSum(sum, red);
    sq  = blockReduceSum(sq, red);
    float mean = sum * (1.f / 400.f);
    float var  = sq * (1.f / 400.f) - mean * mean;
    float rstd = rsqrtf(var + 1e-6f);
    float t0 = 0.f, t1 = 0.f;
    for (int i = 0; i < cnt; i++) {
        int d = dIdx[i];
        float o = (sv[i] - mean) * rstd * ln1g[d] + ln1b[d];
        o1[i] = o;
        t0 = fmaf(o, w1[2 * d], t0);
        t1 = fmaf(o, w1[2 * d + 1], t1);
    }
    t0 = blockReduceSum(t0, red);
    t1 = blockReduceSum(t1, red);
    t0 = fmaxf(t0 + fb1[0], 0.f);
    t1 = fmaxf(t1 + fb1[1], 0.f);
    sum = 0.f; sq = 0.f;
    for (int i = 0; i < cnt; i++) {
        int d = dIdx[i];
        float v = o1[i] + t0 * w2[d] + t1 * w2[400 + d] + fb2[d];
        s2v[i] = v; sum += v; sq += v * v;
    }
    sum = blockReduceSum(sum, red);
    sq  = blockReduceSum(sq, red);
    mean = sum * (1.f / 400.f);
    var  = sq * (1.f / 400.f) - mean * mean;
    rstd = rsqrtf(var + 1e-6f);
    size_t base = (size_t)(b + 1) * 1600 + 1200;
    for (int i = 0; i < cnt; i++) {
        int d = dIdx[i];
        float o = (s2v[i] - mean) * rstd * ln2g[d] + ln2b[d];
        bf16 h = __float2bfloat16(o);
        g_flatH[base + d] = h;
        g_flatL[base + d] = __float2bfloat16(o - __bfloat162float(h));
    }
}

__global__ void gru_elem_kernel(const float* __restrict__ Brow1, int colOff)
{
    int idx = blockIdx.x * 256 + threadIdx.x;
    if (idx >= 16384 * 1800) return;
    int b = idx / 1800, j = idx - b * 1800;
    const float* g = g_G + (size_t)b * 5504;
    float z = 1.f / (1.f + expf(-(g[j] + Brow1[j])));
    float r = 1.f / (1.f + expf(-(g[1800 + j] + Brow1[1800 + j])));
    float hv = g[3600 + j] + r * Brow1[3600 + j];
    float hh = (hv > 0.f) ? hv : expm1f(hv);
    float h = (1.f - z) * hh;
    size_t o = (size_t)b * 3648 + colOff + j;
    bf16 hb = __float2bfloat16(h);
    g_x1H[o] = hb;
    g_x1L[o] = __float2bfloat16(h - __bfloat162float(hb));
}

// ============================ host ============================
#define HM_SMEM (2 * STAGE_B)   // 81920

static void hm_launch(int epi, int nTiles,
                      const bf16* A1H, const bf16* A1L, const bf16* A2H, const bf16* A2L,
                      const bf16* A3H, const bf16* A3L,
                      int lda1, int lda2, int lda3, int kb1, int kb2, int Ktot,
                      const bf16* BH, const bf16* BL, int ldb,
                      float* C, int ldc, const float* bias, int biasN,
                      bf16* OH, bf16* OL, int ldo, int Nvalid)
{
    dim3 grid(nTiles, 128);
    if (epi == 0)
        hmma_gemm<0><<<grid, 256, HM_SMEM>>>(A1H, A1L, A2H, A2L, A3H, A3L, lda1, lda2, lda3,
                                             kb1, kb2, Ktot, BH, BL, ldb, C, ldc, bias, biasN, OH, OL, ldo, Nvalid);
    else if (epi == 1)
        hmma_gemm<1><<<grid, 256, HM_SMEM>>>(A1H, A1L, A2H, A2L, A3H, A3L, lda1, lda2, lda3,
                                             kb1, kb2, Ktot, BH, BL, ldb, C, ldc, bias, biasN, OH, OL, ldo, Nvalid);
    else
        hmma_gemm<2><<<grid, 256, HM_SMEM>>>(A1H, A1L, A2H, A2L, A3H, A3L, lda1, lda2, lda3,
                                             kb1, kb2, Ktot, BH, BL, ldb, C, ldc, bias, biasN, OH, OL, ldo, Nvalid);
}

extern "C" void kernel_launch(void* const* d_in, const int* in_sizes, int n_in,
                              void* d_out, int out_size)
{
    (void)n_in; (void)out_size;
    const float* x  = (const float*)d_in[0];
    const float* Wv = (const float*)d_in[5];
    const float* bv = (const float*)d_in[6];
    const float* Wo = (const float*)d_in[7];
    const float* bo = (const float*)d_in[8];

    bool sigOrder = (in_sizes[10] == 400);
    const float *ln1g, *ln1b, *w1, *fb1, *w2, *fb2, *ln2g, *ln2b;
    const float *gfk, *gfb, *gbk, *gbb, *d2w, *d2b, *d4w, *d4b, *ow, *ob;
    if (sigOrder) {
        ln1g = (const float*)d_in[9];  ln1b = (const float*)d_in[10];
        w1   = (const float*)d_in[11]; fb1  = (const float*)d_in[12];
        w2   = (const float*)d_in[13]; fb2  = (const float*)d_in[14];
        ln2g = (const float*)d_in[15]; ln2b = (const float*)d_in[16];
        gfk  = (const float*)d_in[17]; gfb  = (const float*)d_in[19];
        gbk  = (const float*)d_in[20]; gbb  = (const float*)d_in[22];
        d2w  = (const float*)d_in[23]; d2b  = (const float*)d_in[24];
        d4w  = (const float*)d_in[25]; d4b  = (const float*)d_in[26];
        ow   = (const float*)d_in[27]; ob   = (const float*)d_in[28];
    } else {
        ln1b = (const float*)d_in[9];
        w1   = (const float*)d_in[10]; fb1  = (const float*)d_in[11];
        w2   = (const float*)d_in[12]; fb2  = (const float*)d_in[13];
        ln2b = (const float*)d_in[14];
        gfk  = (const float*)d_in[15]; gfb  = (const float*)d_in[17];
        gbk  = (const float*)d_in[18]; gbb  = (const float*)d_in[20];
        d2w  = (const float*)d_in[21]; d2b  = (const float*)d_in[22];
        d4w  = (const float*)d_in[23]; d4b  = (const float*)d_in[24];
        ow   = (const float*)d_in[25]; ob   = (const float*)d_in[26];
        ln1g = (const float*)d_in[27]; ln2g = (const float*)d_in[28];
    }

    float *pWeff, *pbeff, *pattn, *pG;
    bf16 *pflatH, *pflatL, *px1H, *px1L, *px3H, *px3L, *px5H, *px5L;
    bf16 *pBgfH, *pBgfL, *pBgbH, *pBgbL, *pBd2H, *pBd2L, *pBd4H, *pBd4L, *pBoH, *pBoL;
    cudaGetSymbolAddress((void**)&pWeff, g_Weff);
    cudaGetSymbolAddress((void**)&pbeff, g_beff);
    cudaGetSymbolAddress((void**)&pattn, g_attn);
    cudaGetSymbolAddress((void**)&pG, g_G);
    cudaGetSymbolAddress((void**)&pflatH, g_flatH);
    cudaGetSymbolAddress((void**)&pflatL, g_flatL);
    cudaGetSymbolAddress((void**)&px1H, g_x1H);
    cudaGetSymbolAddress((void**)&px1L, g_x1L);
    cudaGetSymbolAddress((void**)&px3H, g_x3H);
    cudaGetSymbolAddress((void**)&px3L, g_x3L);
    cudaGetSymbolAddress((void**)&px5H, g_x5H);
    cudaGetSymbolAddress((void**)&px5L, g_x5L);
    cudaGetSymbolAddress((void**)&pBgfH, g_BgfH);
    cudaGetSymbolAddress((void**)&pBgfL, g_BgfL);
    cudaGetSymbolAddress((void**)&pBgbH, g_BgbH);
    cudaGetSymbolAddress((void**)&pBgbL, g_BgbL);
    cudaGetSymbolAddress((void**)&pBd2H, g_Bd2H);
    cudaGetSymbolAddress((void**)&pBd2L, g_Bd2L);
    cudaGetSymbolAddress((void**)&pBd4H, g_Bd4H);
    cudaGetSymbolAddress((void**)&pBd4L, g_Bd4L);
    cudaGetSymbolAddress((void**)&pBoH, g_BoH);
    cudaGetSymbolAddress((void**)&pBoL, g_BoL);
    float* out = (float*)d_out;

    cudaFuncSetAttribute(hmma_gemm<0>, cudaFuncAttributeMaxDynamicSharedMemorySize, HM_SMEM);
    cudaFuncSetAttribute(hmma_gemm<1>, cudaFuncAttributeMaxDynamicSharedMemorySize, HM_SMEM);
    cudaFuncSetAttribute(hmma_gemm<2>, cudaFuncAttributeMaxDynamicSharedMemorySize, HM_SMEM);

    // --- front-end (SIMT fp32) ---
    zero_weff_kernel<<<(400 * 400 + 255) / 256, 256>>>();
    {   // W_eff = Wv_flat @ Wo_flat (split-K atomic)
        dim3 g(4, 4, 8);
        sgemm_kernel<<<g, 256>>>(Wv, Wo, pWeff, nullptr, 400, 400, 6400, 6400, 400, 400, 4, 800);
    }
    beff_kernel<<<2, 256>>>(bv, Wo, bo);
    {   // attn = xe @ W_eff + b_eff
        dim3 g(4, 128, 1);
        sgemm_kernel<<<g, 256>>>(x + 2000, pWeff, pattn, pbeff, 16383, 400, 400, 1200, 400, 400, 0, 400);
    }
    build_flat_bf16<<<(16384 * 1200 + 400 + 255) / 256, 256>>>(x);
    frontend_kernel<<<16383, 256>>>(x, ln1g, ln1b, w1, fb1, w2, fb2, ln2g, ln2b);

    // --- weight conversion (transpose + hi/lo split, padded) ---
    { dim3 g(1600 / 32, 5504 / 32); convB_kernel<<<g, dim3(32, 8)>>>(gfk, 1600, 5400, 5400, pBgfH, pBgfL, 1600, 0); }
    { dim3 g(1600 / 32, 5504 / 32); convB_kernel<<<g, dim3(32, 8)>>>(gbk, 1600, 5400, 5400, pBgbH, pBgbL, 1600, 0); }
    { dim3 g(3648 / 32, 1920 / 32); convB_kernel<<<g, dim3(32, 8)>>>(d2w, 3600, 1800, 1800, pBd2H, pBd2L, 3648, 0); }
    { dim3 g(1920 / 32, 1920 / 32); convB_kernel<<<g, dim3(32, 8)>>>(d4w, 1800, 1800, 1800, pBd4H, pBd4L, 1920, 0); }
    { dim3 g(3648 / 32, 256 / 32);  convB_kernel<<<g, dim3(32, 8)>>>(ow,              3600, 140, 140, pBoH, pBoL, 7488, 0); }
    { dim3 g(1920 / 32, 256 / 32);  convB_kernel<<<g, dim3(32, 8)>>>(ow + 3600 * 140, 1800, 140, 140, pBoH, pBoL, 7488, 3648); }
    { dim3 g(1920 / 32, 256 / 32);  convB_kernel<<<g, dim3(32, 8)>>>(ow + 5400 * 140, 1800, 140, 140, pBoH, pBoL, 7488, 5568); }
    pad_x1_kernel<<<(16384 * 48 + 255) / 256, 256>>>();

    // --- tensor-core GEMMs (mma.sync bf16, 3-term compensated) ---
    hm_launch(0, 43, pflatH, pflatL, pflatH, pflatL, pflatH, pflatL, 1600, 1600, 1600, 1600, 1600, 1600,
              pBgfH, pBgfL, 1600, pG, 5504, gfb, 5400, nullptr, nullptr, 0, 5504);
    gru_elem_kernel<<<(16384 * 1800 + 255) / 256, 256>>>(gfb + 5400, 0);
    hm_launch(0, 43, pflatH, pflatL, pflatH, pflatL, pflatH, pflatL, 1600, 1600, 1600, 1600, 1600, 1600,
              pBgbH, pBgbL, 1600, pG, 5504, gbb, 5400, nullptr, nullptr, 0, 5504);
    gru_elem_kernel<<<(16384 * 1800 + 255) / 256, 256>>>(gbb + 5400, 1800);
    hm_launch(1, 15, px1H, px1L, px1H, px1L, px1H, px1L, 3648, 3648, 3648, 3648, 3648, 3648,
              pBd2H, pBd2L, 3648, nullptr, 0, d2b, 1800, px3H, px3L, 1920, 1920);
    hm_launch(1, 15, px3H, px3L, px3H, px3L, px3H, px3L, 1920, 1920, 1920, 1920, 1920, 1920,
              pBd4H, pBd4L, 1920, nullptr, 0, d4b, 1800, px5H, px5L, 1920, 1920);
    hm_launch(2, 2, px1H, px1L, px3H, px3L, px5H, px5L, 3648, 1920, 1920, 3648, 5568, 7488,
              pBoH, pBoL, 7488, out, 140, ob, 140, nullptr, nullptr, 0, 140);
}

// round 8
// speedup vs baseline: 2.8350x; 1.1724x over previous
#include <cuda_runtime.h>
#include <cuda_bf16.h>
#include <math.h>
#include <stdint.h>

typedef __nv_bfloat16 bf16;

// ============================ scratch ============================
__device__ float g_Weff[400 * 400];
__device__ float g_beff[400];
__device__ float g_attn[16383 * 400];
__device__ float g_G[(size_t)16384 * 5504];
__device__ bf16  g_flatH[(size_t)16384 * 1600];
__device__ bf16  g_flatL[(size_t)16384 * 1600];
__device__ bf16  g_x1H[(size_t)16384 * 3648];
__device__ bf16  g_x1L[(size_t)16384 * 3648];
__device__ bf16  g_x3H[(size_t)16384 * 1920];
__device__ bf16  g_x3L[(size_t)16384 * 1920];
__device__ bf16  g_x5H[(size_t)16384 * 1920];
__device__ bf16  g_x5L[(size_t)16384 * 1920];
__device__ bf16  g_BgfH[(size_t)5504 * 1600];
__device__ bf16  g_BgfL[(size_t)5504 * 1600];
__device__ bf16  g_BgbH[(size_t)5504 * 1600];
__device__ bf16  g_BgbL[(size_t)5504 * 1600];
__device__ bf16  g_Bd2H[(size_t)1920 * 3648];
__device__ bf16  g_Bd2L[(size_t)1920 * 3648];
__device__ bf16  g_Bd4H[(size_t)1920 * 1920];
__device__ bf16  g_Bd4L[(size_t)1920 * 1920];
__device__ bf16  g_BoH[(size_t)256 * 7488];
__device__ bf16  g_BoL[(size_t)256 * 7488];

// ============================ ptx helpers (plain sm_103-legal) ============================
__device__ __forceinline__ uint32_t s2u(const void* p) {
    uint32_t a;
    asm("{ .reg .u64 t; cvta.to.shared.u64 t, %1; cvt.u32.u64 %0, t; }" : "=r"(a) : "l"(p));
    return a;
}
__device__ __forceinline__ void ldm_x4(uint32_t* r, uint32_t addr) {
    asm volatile("ldmatrix.sync.aligned.m8n8.x4.shared.b16 {%0,%1,%2,%3}, [%4];"
                 : "=r"(r[0]), "=r"(r[1]), "=r"(r[2]), "=r"(r[3]) : "r"(addr));
}
__device__ __forceinline__ void mma16816(float* c, const uint32_t* a, const uint32_t* b) {
    asm volatile("mma.sync.aligned.m16n8k16.row.col.f32.bf16.bf16.f32 "
                 "{%0,%1,%2,%3}, {%4,%5,%6,%7}, {%8,%9}, {%0,%1,%2,%3};"
                 : "+f"(c[0]), "+f"(c[1]), "+f"(c[2]), "+f"(c[3])
                 : "r"(a[0]), "r"(a[1]), "r"(a[2]), "r"(a[3]), "r"(b[0]), "r"(b[1]));
}
__device__ __forceinline__ void cp16(uint32_t saddr, const void* g) {
    asm volatile("cp.async.cg.shared.global [%0], [%1], 16;" :: "r"(saddr), "l"(g) : "memory");
}

// ============================ HMMA GEMM ============================
// C[16384, 128*gridX] = concat(A1|A2|A3)[16384, Ktot] @ Bt[Npad, Ktot]^T
// bf16 hi/lo 3-term compensation (HH + HL + LH), fp32 register accum.
// EPI 0: C = acc + bias(col<biasN). EPI 1: elu(acc+bias) -> bf16 hi/lo OH/OL.
// EPI 2: C[col<Nvalid] = acc + bias.
#define PITCH 40                   // bf16 elems per smem row (80B; conflict-free)
#define TILE_B (128 * PITCH * 2)   // 10240
#define STAGE_B (4 * TILE_B)       // 40960

template<int EPI>
__global__ __launch_bounds__(256, 2)
void hmma_gemm(const bf16* __restrict__ A1H, const bf16* __restrict__ A1L,
               const bf16* __restrict__ A2H, const bf16* __restrict__ A2L,
               const bf16* __restrict__ A3H, const bf16* __restrict__ A3L,
               int lda1, int lda2, int lda3, int kb1, int kb2, int Ktot,
               const bf16* __restrict__ BH, const bf16* __restrict__ BL, int ldb,
               float* __restrict__ C, int ldc,
               const float* __restrict__ bias, int biasN,
               bf16* __restrict__ OH, bf16* __restrict__ OL, int ldo, int Nvalid)
{
    extern __shared__ char smem[];
    const uint32_t su = s2u(smem);
    const int tid = threadIdx.x;
    const int lane = tid & 31;
    const int wid = tid >> 5;
    const int warp_m = wid & 1;       // 2 x 64 rows
    const int warp_n = wid >> 1;      // 4 x 32 cols
    const size_t rowA = (size_t)blockIdx.y * 128;
    const size_t rowB = (size_t)blockIdx.x * 128;
    const int NCH = Ktot / 32;

    const int ldRow0 = tid >> 2, ldC0 = (tid & 3);
    const int ldRow1 = (tid + 256) >> 2, ldC1 = ldC0;

    auto issue = [&](int ch, int s) {
        const int k0 = ch * 32;
        const bf16 *pAH, *pAL; int kl; size_t lda;
        if (k0 < kb1)      { pAH = A1H; pAL = A1L; kl = k0;       lda = (size_t)lda1; }
        else if (k0 < kb2) { pAH = A2H; pAL = A2L; kl = k0 - kb1; lda = (size_t)lda2; }
        else               { pAH = A3H; pAL = A3L; kl = k0 - kb2; lda = (size_t)lda3; }
        uint32_t st = su + s * STAGE_B;
        uint32_t d0 = st + ldRow0 * (PITCH * 2) + ldC0 * 16;
        uint32_t d1 = st + ldRow1 * (PITCH * 2) + ldC1 * 16;
        size_t a0 = (rowA + ldRow0) * lda + kl + ldC0 * 8;
        size_t a1 = (rowA + ldRow1) * lda + kl + ldC1 * 8;
        size_t b0 = (rowB + ldRow0) * (size_t)ldb + k0 + ldC0 * 8;
        size_t b1 = (rowB + ldRow1) * (size_t)ldb + k0 + ldC1 * 8;
        cp16(d0,              pAH + a0);  cp16(d1,              pAH + a1);
        cp16(d0 + TILE_B,     pAL + a0);  cp16(d1 + TILE_B,     pAL + a1);
        cp16(d0 + 2 * TILE_B, BH  + b0);  cp16(d1 + 2 * TILE_B, BH  + b1);
        cp16(d0 + 3 * TILE_B, BL  + b0);  cp16(d1 + 3 * TILE_B, BL  + b1);
        asm volatile("cp.async.commit_group;" ::: "memory");
    };

    float acc[4][4][4];
#pragma unroll
    for (int i = 0; i < 4; i++)
#pragma unroll
        for (int j = 0; j < 4; j++)
#pragma unroll
            for (int k = 0; k < 4; k++) acc[i][j][k] = 0.f;

    issue(0, 0);

    const int aLRow = lane & 15, aKH = lane >> 4;
    const int bRow = (lane & 7) + ((lane >> 4) << 3);
    const int bKH = (lane >> 3) & 1;

    for (int ch = 0; ch < NCH; ch++) {
        const int s = ch & 1;
        asm volatile("cp.async.wait_group 0;" ::: "memory");
        __syncthreads();
        if (ch + 1 < NCH) issue(ch + 1, s ^ 1);

        const uint32_t st = su + s * STAGE_B;
#pragma unroll
        for (int kk2 = 0; kk2 < 2; kk2++) {
            const int kcol = kk2 * 16;
            // B fragments for all 4 nf (hi & lo)
            uint32_t bH[4][2], bL[4][2];
#pragma unroll
            for (int np = 0; np < 2; np++) {
                uint32_t ad = st + 2 * TILE_B + (warp_n * 32 + np * 16 + bRow) * (PITCH * 2) + (kcol + 8 * bKH) * 2;
                uint32_t t[4];
                ldm_x4(t, ad);
                bH[np * 2][0] = t[0]; bH[np * 2][1] = t[1];
                bH[np * 2 + 1][0] = t[2]; bH[np * 2 + 1][1] = t[3];
                ldm_x4(t, ad + TILE_B);
                bL[np * 2][0] = t[0]; bL[np * 2][1] = t[1];
                bL[np * 2 + 1][0] = t[2]; bL[np * 2 + 1][1] = t[3];
            }
            // Two halves of mf to bound register pressure
#pragma unroll
            for (int mh = 0; mh < 2; mh++) {
                uint32_t aH[2][4], aL[2][4];
#pragma unroll
                for (int i = 0; i < 2; i++) {
                    uint32_t ad = st + (warp_m * 64 + (mh * 2 + i) * 16 + aLRow) * (PITCH * 2) + (kcol + 8 * aKH) * 2;
                    ldm_x4(aH[i], ad);
                    ldm_x4(aL[i], ad + TILE_B);
                }
                // Term-ordered: HH x8, HL x8, LH x8 — accumulator reuse distance 8
#pragma unroll
                for (int i = 0; i < 2; i++)
#pragma unroll
                    for (int nf = 0; nf < 4; nf++)
                        mma16816(acc[mh * 2 + i][nf], aH[i], bH[nf]);
#pragma unroll
                for (int i = 0; i < 2; i++)
#pragma unroll
                    for (int nf = 0; nf < 4; nf++)
                        mma16816(acc[mh * 2 + i][nf], aH[i], bL[nf]);
#pragma unroll
                for (int i = 0; i < 2; i++)
#pragma unroll
                    for (int nf = 0; nf < 4; nf++)
                        mma16816(acc[mh * 2 + i][nf], aL[i], bH[nf]);
            }
        }
    }

    // ---------------- epilogue ----------------
    const int rBase = (int)rowA + warp_m * 64 + (lane >> 2);
    const int cBase = (int)rowB + warp_n * 32 + (lane & 3) * 2;
#pragma unroll
    for (int mf = 0; mf < 4; mf++) {
#pragma unroll
        for (int half = 0; half < 2; half++) {
            const size_t r = rBase + mf * 16 + half * 8;
#pragma unroll
            for (int nf = 0; nf < 4; nf++) {
                const int col = cBase + nf * 8;
                float v0 = acc[mf][nf][half * 2 + 0];
                float v1 = acc[mf][nf][half * 2 + 1];
                if (EPI == 0) {
                    if (col + 0 < biasN) v0 += bias[col + 0];
                    if (col + 1 < biasN) v1 += bias[col + 1];
                    *reinterpret_cast<float2*>(C + r * (size_t)ldc + col) = make_float2(v0, v1);
                } else if (EPI == 1) {
                    if (col + 0 < biasN) v0 += bias[col + 0];
                    if (col + 1 < biasN) v1 += bias[col + 1];
                    v0 = v0 > 0.f ? v0 : expm1f(v0);
                    v1 = v1 > 0.f ? v1 : expm1f(v1);
                    bf16 h0 = __float2bfloat16(v0), h1 = __float2bfloat16(v1);
                    bf16 l0 = __float2bfloat16(v0 - __bfloat162float(h0));
                    bf16 l1 = __float2bfloat16(v1 - __bfloat162float(h1));
                    uint32_t hp = (uint32_t)__bfloat16_as_ushort(h0) | ((uint32_t)__bfloat16_as_ushort(h1) << 16);
                    uint32_t lp = (uint32_t)__bfloat16_as_ushort(l0) | ((uint32_t)__bfloat16_as_ushort(l1) << 16);
                    *reinterpret_cast<uint32_t*>(OH + r * (size_t)ldo + col) = hp;
                    *reinterpret_cast<uint32_t*>(OL + r * (size_t)ldo + col) = lp;
                } else {
                    if (col + 0 < Nvalid) C[r * (size_t)ldc + col + 0] = v0 + bias[col + 0];
                    if (col + 1 < Nvalid) C[r * (size_t)ldc + col + 1] = v1 + bias[col + 1];
                }
            }
        }
    }
}

// ============================ weight transpose + split ============================
__global__ void convB_kernel(const float* __restrict__ B, int Ksrc, int Nsrc, int ldbsrc,
                             bf16* __restrict__ BtH, bf16* __restrict__ BtL, int ldbt, int kOff)
{
    __shared__ float t[32][33];
    int k0 = blockIdx.x * 32, n0 = blockIdx.y * 32;
    int tx = threadIdx.x, ty = threadIdx.y;
#pragma unroll
    for (int i = 0; i < 4; i++) {
        int k = k0 + ty + i * 8, n = n0 + tx;
        t[ty + i * 8][tx] = (k < Ksrc && n < Nsrc) ? B[(size_t)k * ldbsrc + n] : 0.f;
    }
    __syncthreads();
#pragma unroll
    for (int i = 0; i < 4; i++) {
        int n = n0 + ty + i * 8, k = k0 + tx;
        float v = t[tx][ty + i * 8];
        bf16 h = __float2bfloat16(v);
        size_t o = (size_t)n * ldbt + kOff + k;
        BtH[o] = h;
        BtL[o] = __float2bfloat16(v - __bfloat162float(h));
    }
}

// ============================ SIMT SGEMM (front-end only) ============================
#define BM 128
#define BN 128
#define BK 8
__global__ __launch_bounds__(256, 2)
void sgemm_kernel(const float* __restrict__ A, const float* __restrict__ B,
                  float* __restrict__ C, const float* __restrict__ bias,
                  int M, int N, int K, int lda, int ldb, int ldc, int flags, int kChunk)
{
    __shared__ float As[BK][BM];
    __shared__ float Bs[BK][BN];
    const int tid = threadIdx.x;
    const int tx = tid & 15, ty = tid >> 4;
    const int rowBase = blockIdx.y * BM, colBase = blockIdx.x * BN;
    const int kStart = blockIdx.z * kChunk;
    const int kEnd = min(kStart + kChunk, K);
    float acc[8][8];
#pragma unroll
    for (int i = 0; i < 8; i++)
#pragma unroll
        for (int j = 0; j < 8; j++) acc[i][j] = 0.f;
    const int aRow = tid >> 1, aCol = (tid & 1) * 4, gARow = rowBase + aRow;
    const int bRow = tid >> 5, bCol = (tid & 31) * 4, gBCol = colBase + bCol;
    for (int k0 = kStart; k0 < kEnd; k0 += BK) {
        float4 av = make_float4(0.f, 0.f, 0.f, 0.f);
        if (gARow < M) av = *reinterpret_cast<const float4*>(A + (size_t)gARow * lda + k0 + aCol);
        As[aCol + 0][aRow] = av.x; As[aCol + 1][aRow] = av.y;
        As[aCol + 2][aRow] = av.z; As[aCol + 3][aRow] = av.w;
        float4 bv = make_float4(0.f, 0.f, 0.f, 0.f);
        if (gBCol < N) bv = *reinterpret_cast<const float4*>(B + (size_t)(k0 + bRow) * ldb + gBCol);
        *reinterpret_cast<float4*>(&Bs[bRow][bCol]) = bv;
        __syncthreads();
#pragma unroll
        for (int kk = 0; kk < BK; kk++) {
            float4 a0 = *reinterpret_cast<const float4*>(&As[kk][ty * 8]);
            float4 a1 = *reinterpret_cast<const float4*>(&As[kk][ty * 8 + 4]);
            float4 b0 = *reinterpret_cast<const float4*>(&Bs[kk][tx * 8]);
            float4 b1 = *reinterpret_cast<const float4*>(&Bs[kk][tx * 8 + 4]);
            float a[8] = {a0.x, a0.y, a0.z, a0.w, a1.x, a1.y, a1.z, a1.w};
            float b[8] = {b0.x, b0.y, b0.z, b0.w, b1.x, b1.y, b1.z, b1.w};
#pragma unroll
            for (int i = 0; i < 8; i++)
#pragma unroll
                for (int j = 0; j < 8; j++) acc[i][j] = fmaf(a[i], b[j], acc[i][j]);
        }
        __syncthreads();
    }
#pragma unroll
    for (int i = 0; i < 8; i++) {
        int row = rowBase + ty * 8 + i;
        if (row >= M) continue;
#pragma unroll
        for (int j = 0; j < 8; j++) {
            int col = colBase + tx * 8 + j;
            if (col >= N) continue;
            float v = acc[i][j];
            size_t off = (size_t)row * ldc + col;
            if (flags & 4) atomicAdd(&C[off], v);
            else { if (bias) v += bias[col]; C[off] = v; }
        }
    }
}

// ============================ small helpers ============================
__global__ void zero_weff_kernel()
{
    int i = blockIdx.x * 256 + threadIdx.x;
    if (i < 400 * 400) g_Weff[i] = 0.f;
}
__global__ void beff_kernel(const float* __restrict__ bv, const float* __restrict__ Wo,
                            const float* __restrict__ bo)
{
    int d = blockIdx.x * 256 + threadIdx.x;
    if (d >= 400) return;
    float acc = bo[d];
    for (int j = 0; j < 6400; j++) acc = fmaf(bv[j], Wo[(size_t)j * 400 + d], acc);
    g_beff[d] = acc;
}
__global__ void build_flat_bf16(const float* __restrict__ x)
{
    int idx = blockIdx.x * 256 + threadIdx.x;
    const int total = 16384 * 1200;
    float v; size_t dst;
    if (idx < total) {
        int b = idx / 1200, c = idx - b * 1200;
        v = x[idx]; dst = (size_t)b * 1600 + c;
    } else if (idx < total + 400) {
        int d = idx - total;
        v = x[800 + d]; dst = 1200 + d;
    } else return;
    bf16 h = __float2bfloat16(v);
    g_flatH[dst] = h;
    g_flatL[dst] = __float2bfloat16(v - __bfloat162float(h));
}
__global__ void pad_x1_kernel()
{
    int i = blockIdx.x * 256 + threadIdx.x;
    if (i >= 16384 * 48) return;
    int b = i / 48, c = 3600 + i % 48;
    size_t o = (size_t)b * 3648 + c;
    g_x1H[o] = __float2bfloat16(0.f);
    g_x1L[o] = __float2bfloat16(0.f);
}

__device__ __forceinline__ float blockReduceSum(float v, float* sh)
{
#pragma unroll
    for (int o = 16; o > 0; o >>= 1) v += __shfl_xor_sync(0xffffffffu, v, o);
    int lane = threadIdx.x & 31, warp = threadIdx.x >> 5;
    if (lane == 0) sh[warp] = v;
    __syncthreads();
    if (warp == 0) {
        float r = (lane < 8) ? sh[lane] : 0.f;
#pragma unroll
        for (int o = 4; o > 0; o >>= 1) r += __shfl_xor_sync(0xffffffffu, r, o);
        if (lane == 0) sh[0] = r;
    }
    __syncthreads();
    float r = sh[0];
    __syncthreads();
    return r;
}

__global__ __launch_bounds__(256)
void frontend_kernel(const float* __restrict__ x,
                     const float* __restrict__ ln1g, const float* __restrict__ ln1b,
                     const float* __restrict__ w1,  const float* __restrict__ fb1,
                     const float* __restrict__ w2,  const float* __restrict__ fb2,
                     const float* __restrict__ ln2g, const float* __restrict__ ln2b)
{
    int b = blockIdx.x;
    const float* xe = x + (size_t)(b + 1) * 1200 + 800;
    const float* at = g_attn + (size_t)b * 400;
    __shared__ float red[32];
    int t = threadIdx.x;
    float sv[2], o1[2], s2v[2];
    int dIdx[2], cnt = 0;
    float sum = 0.f, sq = 0.f;
    for (int d = t; d < 400; d += 256) {
        float v = xe[d] + at[d];
        sv[cnt] = v; dIdx[cnt] = d; cnt++;
        sum += v; sq += v * v;
    }
    sum = blockReduceSum(sum, red);
    sq  = blockReduceSum(sq, red);
    float mean = sum * (1.f / 400.f);
    float var  = sq * (1.f / 400.f) - mean * mean;
    float rstd = rsqrtf(var + 1e-6f);
    float t0 = 0.f, t1 = 0.f;
    for (int i = 0; i < cnt; i++) {
        int d = dIdx[i];
        float o = (sv[i] - mean) * rstd * ln1g[d] + ln1b[d];
        o1[i] = o;
        t0 = fmaf(o, w1[2 * d], t0);
        t1 = fmaf(o, w1[2 * d + 1], t1);
    }
    t0 = blockReduceSum(t0, red);
    t1 = blockReduceSum(t1, red);
    t0 = fmaxf(t0 + fb1[0], 0.f);
    t1 = fmaxf(t1 + fb1[1], 0.f);
    sum = 0.f; sq = 0.f;
    for (int i = 0; i < cnt; i++) {
        int d = dIdx[i];
        float v = o1[i] + t0 * w2[d] + t1 * w2[400 + d] + fb2[d];
        s2v[i] = v; sum += v; sq += v * v;
    }
    sum = blockReduceSum(sum, red);
    sq  = blockReduceSum(sq, red);
    mean = sum * (1.f / 400.f);
    var  = sq * (1.f / 400.f) - mean * mean;
    rstd = rsqrtf(var + 1e-6f);
    size_t base = (size_t)(b + 1) * 1600 + 1200;
    for (int i = 0; i < cnt; i++) {
        int d = dIdx[i];
        float o = (s2v[i] - mean) * rstd * ln2g[d] + ln2b[d];
        bf16 h = __float2bfloat16(o);
        g_flatH[base + d] = h;
        g_flatL[base + d] = __float2bfloat16(o - __bfloat162float(h));
    }
}

__global__ void gru_elem_kernel(const float* __restrict__ Brow1, int colOff)
{
    int idx = blockIdx.x * 256 + threadIdx.x;
    if (idx >= 16384 * 1800) return;
    int b = idx / 1800, j = idx - b * 1800;
    const float* g = g_G + (size_t)b * 5504;
    float z = 1.f / (1.f + expf(-(g[j] + Brow1[j])));
    float r = 1.f / (1.f + expf(-(g[1800 + j] + Brow1[1800 + j])));
    float hv = g[3600 + j] + r * Brow1[3600 + j];
    float hh = (hv > 0.f) ? hv : expm1f(hv);
    float h = (1.f - z) * hh;
    size_t o = (size_t)b * 3648 + colOff + j;
    bf16 hb = __float2bfloat16(h);
    g_x1H[o] = hb;
    g_x1L[o] = __float2bfloat16(h - __bfloat162float(hb));
}

// ============================ host ============================
#define HM_SMEM (2 * STAGE_B)   // 81920

static void hm_launch(int epi, int nTiles,
                      const bf16* A1H, const bf16* A1L, const bf16* A2H, const bf16* A2L,
                      const bf16* A3H, const bf16* A3L,
                      int lda1, int lda2, int lda3, int kb1, int kb2, int Ktot,
                      const bf16* BH, const bf16* BL, int ldb,
                      float* C, int ldc, const float* bias, int biasN,
                      bf16* OH, bf16* OL, int ldo, int Nvalid)
{
    dim3 grid(nTiles, 128);
    if (epi == 0)
        hmma_gemm<0><<<grid, 256, HM_SMEM>>>(A1H, A1L, A2H, A2L, A3H, A3L, lda1, lda2, lda3,
                                             kb1, kb2, Ktot, BH, BL, ldb, C, ldc, bias, biasN, OH, OL, ldo, Nvalid);
    else if (epi == 1)
        hmma_gemm<1><<<grid, 256, HM_SMEM>>>(A1H, A1L, A2H, A2L, A3H, A3L, lda1, lda2, lda3,
                                             kb1, kb2, Ktot, BH, BL, ldb, C, ldc, bias, biasN, OH, OL, ldo, Nvalid);
    else
        hmma_gemm<2><<<grid, 256, HM_SMEM>>>(A1H, A1L, A2H, A2L, A3H, A3L, lda1, lda2, lda3,
                                             kb1, kb2, Ktot, BH, BL, ldb, C, ldc, bias, biasN, OH, OL, ldo, Nvalid);
}

extern "C" void kernel_launch(void* const* d_in, const int* in_sizes, int n_in,
                              void* d_out, int out_size)
{
    (void)n_in; (void)out_size;
    const float* x  = (const float*)d_in[0];
    const float* Wv = (const float*)d_in[5];
    const float* bv = (const float*)d_in[6];
    const float* Wo = (const float*)d_in[7];
    const float* bo = (const float*)d_in[8];

    bool sigOrder = (in_sizes[10] == 400);
    const float *ln1g, *ln1b, *w1, *fb1, *w2, *fb2, *ln2g, *ln2b;
    const float *gfk, *gfb, *gbk, *gbb, *d2w, *d2b, *d4w, *d4b, *ow, *ob;
    if (sigOrder) {
        ln1g = (const float*)d_in[9];  ln1b = (const float*)d_in[10];
        w1   = (const float*)d_in[11]; fb1  = (const float*)d_in[12];
        w2   = (const float*)d_in[13]; fb2  = (const float*)d_in[14];
        ln2g = (const float*)d_in[15]; ln2b = (const float*)d_in[16];
        gfk  = (const float*)d_in[17]; gfb  = (const float*)d_in[19];
        gbk  = (const float*)d_in[20]; gbb  = (const float*)d_in[22];
        d2w  = (const float*)d_in[23]; d2b  = (const float*)d_in[24];
        d4w  = (const float*)d_in[25]; d4b  = (const float*)d_in[26];
        ow   = (const float*)d_in[27]; ob   = (const float*)d_in[28];
    } else {
        ln1b = (const float*)d_in[9];
        w1   = (const float*)d_in[10]; fb1  = (const float*)d_in[11];
        w2   = (const float*)d_in[12]; fb2  = (const float*)d_in[13];
        ln2b = (const float*)d_in[14];
        gfk  = (const float*)d_in[15]; gfb  = (const float*)d_in[17];
        gbk  = (const float*)d_in[18]; gbb  = (const float*)d_in[20];
        d2w  = (const float*)d_in[21]; d2b  = (const float*)d_in[22];
        d4w  = (const float*)d_in[23]; d4b  = (const float*)d_in[24];
        ow   = (const float*)d_in[25]; ob   = (const float*)d_in[26];
        ln1g = (const float*)d_in[27]; ln2g = (const float*)d_in[28];
    }

    float *pWeff, *pbeff, *pattn, *pG;
    bf16 *pflatH, *pflatL, *px1H, *px1L, *px3H, *px3L, *px5H, *px5L;
    bf16 *pBgfH, *pBgfL, *pBgbH, *pBgbL, *pBd2H, *pBd2L, *pBd4H, *pBd4L, *pBoH, *pBoL;
    cudaGetSymbolAddress((void**)&pWeff, g_Weff);
    cudaGetSymbolAddress((void**)&pbeff, g_beff);
    cudaGetSymbolAddress((void**)&pattn, g_attn);
    cudaGetSymbolAddress((void**)&pG, g_G);
    cudaGetSymbolAddress((void**)&pflatH, g_flatH);
    cudaGetSymbolAddress((void**)&pflatL, g_flatL);
    cudaGetSymbolAddress((void**)&px1H, g_x1H);
    cudaGetSymbolAddress((void**)&px1L, g_x1L);
    cudaGetSymbolAddress((void**)&px3H, g_x3H);
    cudaGetSymbolAddress((void**)&px3L, g_x3L);
    cudaGetSymbolAddress((void**)&px5H, g_x5H);
    cudaGetSymbolAddress((void**)&px5L, g_x5L);
    cudaGetSymbolAddress((void**)&pBgfH, g_BgfH);
    cudaGetSymbolAddress((void**)&pBgfL, g_BgfL);
    cudaGetSymbolAddress((void**)&pBgbH, g_BgbH);
    cudaGetSymbolAddress((void**)&pBgbL, g_BgbL);
    cudaGetSymbolAddress((void**)&pBd2H, g_Bd2H);
    cudaGetSymbolAddress((void**)&pBd2L, g_Bd2L);
    cudaGetSymbolAddress((void**)&pBd4H, g_Bd4H);
    cudaGetSymbolAddress((void**)&pBd4L, g_Bd4L);
    cudaGetSymbolAddress((void**)&pBoH, g_BoH);
    cudaGetSymbolAddress((void**)&pBoL, g_BoL);
    float* out = (float*)d_out;

    cudaFuncSetAttribute(hmma_gemm<0>, cudaFuncAttributeMaxDynamicSharedMemorySize, HM_SMEM);
    cudaFuncSetAttribute(hmma_gemm<1>, cudaFuncAttributeMaxDynamicSharedMemorySize, HM_SMEM);
    cudaFuncSetAttribute(hmma_gemm<2>, cudaFuncAttributeMaxDynamicSharedMemorySize, HM_SMEM);

    // --- front-end (SIMT fp32) ---
    zero_weff_kernel<<<(400 * 400 + 255) / 256, 256>>>();
    {   // W_eff = Wv_flat @ Wo_flat (split-K atomic)
        dim3 g(4, 4, 8);
        sgemm_kernel<<<g, 256>>>(Wv, Wo, pWeff, nullptr, 400, 400, 6400, 6400, 400, 400, 4, 800);
    }
    beff_kernel<<<2, 256>>>(bv, Wo, bo);
    {   // attn = xe @ W_eff + b_eff
        dim3 g(4, 128, 1);
        sgemm_kernel<<<g, 256>>>(x + 2000, pWeff, pattn, pbeff, 16383, 400, 400, 1200, 400, 400, 0, 400);
    }
    build_flat_bf16<<<(16384 * 1200 + 400 + 255) / 256, 256>>>(x);
    frontend_kernel<<<16383, 256>>>(x, ln1g, ln1b, w1, fb1, w2, fb2, ln2g, ln2b);

    // --- weight conversion (transpose + hi/lo split, padded) ---
    { dim3 g(1600 / 32, 5504 / 32); convB_kernel<<<g, dim3(32, 8)>>>(gfk, 1600, 5400, 5400, pBgfH, pBgfL, 1600, 0); }
    { dim3 g(1600 / 32, 5504 / 32); convB_kernel<<<g, dim3(32, 8)>>>(gbk, 1600, 5400, 5400, pBgbH, pBgbL, 1600, 0); }
    { dim3 g(3648 / 32, 1920 / 32); convB_kernel<<<g, dim3(32, 8)>>>(d2w, 3600, 1800, 1800, pBd2H, pBd2L, 3648, 0); }
    { dim3 g(1920 / 32, 1920 / 32); convB_kernel<<<g, dim3(32, 8)>>>(d4w, 1800, 1800, 1800, pBd4H, pBd4L, 1920, 0); }
    { dim3 g(3648 / 32, 256 / 32);  convB_kernel<<<g, dim3(32, 8)>>>(ow,              3600, 140, 140, pBoH, pBoL, 7488, 0); }
    { dim3 g(1920 / 32, 256 / 32);  convB_kernel<<<g, dim3(32, 8)>>>(ow + 3600 * 140, 1800, 140, 140, pBoH, pBoL, 7488, 3648); }
    { dim3 g(1920 / 32, 256 / 32);  convB_kernel<<<g, dim3(32, 8)>>>(ow + 5400 * 140, 1800, 140, 140, pBoH, pBoL, 7488, 5568); }
    pad_x1_kernel<<<(16384 * 48 + 255) / 256, 256>>>();

    // --- tensor-core GEMMs (mma.sync bf16, 3-term compensated) ---
    hm_launch(0, 43, pflatH, pflatL, pflatH, pflatL, pflatH, pflatL, 1600, 1600, 1600, 1600, 1600, 1600,
              pBgfH, pBgfL, 1600, pG, 5504, gfb, 5400, nullptr, nullptr, 0, 5504);
    gru_elem_kernel<<<(16384 * 1800 + 255) / 256, 256>>>(gfb + 5400, 0);
    hm_launch(0, 43, pflatH, pflatL, pflatH, pflatL, pflatH, pflatL, 1600, 1600, 1600, 1600, 1600, 1600,
              pBgbH, pBgbL, 1600, pG, 5504, gbb, 5400, nullptr, nullptr, 0, 5504);
    gru_elem_kernel<<<(16384 * 1800 + 255) / 256, 256>>>(gbb + 5400, 1800);
    hm_launch(1, 15, px1H, px1L, px1H, px1L, px1H, px1L, 3648, 3648, 3648, 3648, 3648, 3648,
              pBd2H, pBd2L, 3648, nullptr, 0, d2b, 1800, px3H, px3L, 1920, 1920);
    hm_launch(1, 15, px3H, px3L, px3H, px3L, px3H, px3L, 1920, 1920, 1920, 1920, 1920, 1920,
              pBd4H, pBd4L, 1920, nullptr, 0, d4b, 1800, px5H, px5L, 1920, 1920);
    hm_launch(2, 2, px1H, px1L, px3H, px3L, px5H, px5L, 3648, 1920, 1920, 3648, 5568, 7488,
              pBoH, pBoL, 7488, out, 140, ob, 140, nullptr, nullptr, 0, 140);
}